// round 16
// baseline (speedup 1.0000x reference)
#include <cuda_runtime.h>
#include <cuda_bf16.h>
#include <mma.h>
#include <cstdint>

using namespace nvcuda;

#define H_IMG 224
#define W_IMG 224
#define NPIX (H_IMG * W_IMG)          // 50176
#define BATCH 32
#define KKP 64
#define PATCH 16
#define NCLASS 1000
#define NPATCH (BATCH * KKP)          // 2048
#define FEAT 2048                      // 8*16*16
#define FC1OUT 64
#define FC2IN (KKP * FC1OUT)          // 4096
#define NCHUNK 8
#define CHUNKROWS 28
#define CHUNK (NPIX / NCHUNK)         // 6272
#define FC1_SPLIT 4
#define FC2_SPLIT 16

// dynamic smem layout for fused harris+topk
#define SM_KEYS 0
#define SM_GRAY 25088
#define SM_DXS  (SM_GRAY + 32 * 228 * 4)
#define SM_DYS  (SM_DXS + 30 * 198 * 4)
#define SM_TOPK_TOTAL (SM_DYS + 30 * 198 * 4)  // 101792

// -------------------- device scratch --------------------
__device__ unsigned long long g_cand[BATCH * NCHUNK * KKP];
__device__ int   g_kp[BATCH * KKP];
__device__ __nv_bfloat16 g_H1h[NPATCH * FEAT];
__device__ __nv_bfloat16 g_H1l[NPATCH * FEAT];
__device__ __nv_bfloat16 g_Wh[FC1OUT * FEAT];
__device__ __nv_bfloat16 g_Wl[FC1OUT * FEAT];
__device__ float g_Cpart[FC1_SPLIT * NPATCH * FC1OUT];
__device__ float g_H2T[FC2IN * BATCH];
__device__ float g_F2p[FC2_SPLIT * BATCH * NCLASS];

// ==================== 0. split fc1 weights to bf16 hi/lo ====================
__global__ void __launch_bounds__(256) prep_w(const float* __restrict__ w) {
    int i = blockIdx.x * 256 + threadIdx.x;   // < 131072
    float v = w[i];
    __nv_bfloat16 h = __float2bfloat16(v);
    g_Wh[i] = h;
    g_Wl[i] = __float2bfloat16(v - __bfloat162float(h));
}

// ==================== 1+2. fused Harris + exact per-chunk top-64 ====================
__device__ __forceinline__ unsigned int fkey(float f) {
    unsigned int u = __float_as_uint(f);
    return (u & 0x80000000u) ? ~u : (u | 0x80000000u);
}
__device__ __forceinline__ void hist_add(unsigned int* hist, int bin) {
    unsigned int act = __activemask();
    unsigned int same = __match_any_sync(act, bin);
    int leader = __ffs(same) - 1;
    if ((int)(threadIdx.x & 31) == leader)
        atomicAdd(&hist[bin], (unsigned int)__popc(same));
}

__global__ void __launch_bounds__(512) topk_stage1(const float* __restrict__ x) {
    extern __shared__ char smraw[];
    unsigned int* keys = (unsigned int*)(smraw + SM_KEYS);
    float* gray = (float*)(smraw + SM_GRAY);
    float* dxs  = (float*)(smraw + SM_DXS);
    float* dys  = (float*)(smraw + SM_DYS);

    __shared__ unsigned int hist[256];
    __shared__ unsigned int suf[256];
    __shared__ unsigned int sh_prefix;
    __shared__ int sh_kneed;
    __shared__ unsigned long long cand[64];
    __shared__ int sh_cnt;
    __shared__ int sh_min;

    const int c = blockIdx.x;
    const int b = blockIdx.y;
    const int tid = threadIdx.x;
    const int r0 = c * CHUNKROWS;
    const int base = r0 * W_IMG;
    const float* xb = x + (size_t)b * 3 * NPIX;

    if (tid < 256) hist[tid] = 0u;

    for (int i = tid; i < 32 * W_IMG; i += 512) {
        int gr = i / W_IMG, col = i - (i / W_IMG) * W_IMG;
        int row = r0 - 2 + gr;
        float v = 0.0f;
        if (row >= 0 && row < H_IMG) {
            int off = row * W_IMG + col;
            v = (xb[off] + xb[NPIX + off] + xb[2 * NPIX + off]) / 3.0f;
        }
        gray[gr * 228 + col] = v;
    }
    __syncthreads();

    const int outMin = max(r0, PATCH);
    const int outMax = min(r0 + CHUNKROWS - 1, H_IMG - PATCH - 1);
    const int dRow0 = outMin - 1;
    const int nDRows = outMax + 1 - dRow0 + 1;

    for (int i = tid; i < nDRows * 194; i += 512) {
        int dr = i / 194, dc = i - dr * 194;
        int Y = dRow0 + dr;
        int X = 15 + dc;
        int g0 = (Y - 1 - (r0 - 2)) * 228 + X;
        float gm1l = gray[g0 - 1],        gm1c = gray[g0],        gm1r = gray[g0 + 1];
        float g0l  = gray[g0 + 228 - 1],                          g0r  = gray[g0 + 228 + 1];
        float gp1l = gray[g0 + 456 - 1],  gp1c = gray[g0 + 456],  gp1r = gray[g0 + 456 + 1];
        float lft = gm1l + g0l + gp1l;
        float rgt = gm1r + g0r + gp1r;
        float top = gm1l + gm1c + gm1r;
        float bot = gp1l + gp1c + gp1r;
        dxs[dr * 198 + dc] = rgt - lft;
        dys[dr * 198 + dc] = bot - top;
    }
    __syncthreads();

    const float GW[3][3] = {{0.0625f, 0.125f, 0.0625f},
                            {0.125f,  0.25f,  0.125f},
                            {0.0625f, 0.125f, 0.0625f}};
    for (int i = tid; i < CHUNK; i += 512) {
        int lr = i / W_IMG;
        int col = i - lr * W_IMG;
        int row = r0 + lr;
        unsigned int key = 0x80000000u;
        if (row >= PATCH && row < H_IMG - PATCH && col >= PATCH && col < W_IMG - PATCH) {
            float sxx = 0.f, syy = 0.f, sxy = 0.f;
            int dbase = (row - 1 - dRow0) * 198 + (col - 1 - 15);
#pragma unroll
            for (int u = 0; u < 3; u++)
#pragma unroll
                for (int v = 0; v < 3; v++) {
                    float w = GW[u][v];
                    float a = dxs[dbase + u * 198 + v];
                    float d = dys[dbase + u * 198 + v];
                    sxx += w * (a * a);
                    syy += w * (d * d);
                    sxy += w * (a * d);
                }
            float tr = sxx + syy;
            float R = sxx * syy - sxy * sxy - 0.04f * tr * tr;
            key = fkey(R);
        }
        keys[i] = key;
        hist_add(hist, key >> 24);
    }
    __syncthreads();

    unsigned int prefix = 0;
    int kneed = KKP;
    for (int level = 0; level < 4; level++) {
        int shift = 24 - 8 * level;
        if (level > 0) {
            if (tid < 256) hist[tid] = 0u;
            __syncthreads();
            for (int i = tid; i < CHUNK; i += 512) {
                unsigned int u = keys[i];
                if ((u >> (shift + 8)) == (prefix >> (shift + 8)))
                    hist_add(hist, (u >> shift) & 0xFFu);
            }
            __syncthreads();
        }
        if (tid < 256) suf[tid] = hist[tid];
        __syncthreads();
#pragma unroll
        for (int off = 1; off < 256; off <<= 1) {
            unsigned int add = 0;
            if (tid < 256 && tid + off < 256) add = suf[tid + off];
            __syncthreads();
            if (tid < 256) suf[tid] += add;
            __syncthreads();
        }
        if (tid < 256) {
            unsigned int ge = suf[tid];
            unsigned int gt = (tid == 255) ? 0u : suf[tid + 1];
            if (ge >= (unsigned int)kneed && gt < (unsigned int)kneed) {
                sh_kneed = kneed - (int)gt;
                sh_prefix = prefix | ((unsigned int)tid << shift);
            }
        }
        __syncthreads();
        prefix = sh_prefix;
        kneed = sh_kneed;
        __syncthreads();
    }

    const unsigned int T = prefix;
    const int cGT = KKP - kneed;

    if (tid == 0) sh_cnt = 0;
    __syncthreads();
    for (int i = tid; i < CHUNK; i += 512) {
        unsigned int u = keys[i];
        if (u > T) {
            int pos = atomicAdd(&sh_cnt, 1);
            cand[pos] = (((unsigned long long)(~u)) << 32) | (unsigned long long)(base + i);
        }
    }
    __syncthreads();

    int last = -1;
    for (int t = 0; t < kneed; t++) {
        if (tid == 0) sh_min = CHUNK;
        __syncthreads();
        for (int i = tid; i < CHUNK; i += 512)
            if (i > last && keys[i] == T) atomicMin(&sh_min, i);
        __syncthreads();
        int found = sh_min;
        if (tid == 0)
            cand[cGT + t] = (((unsigned long long)(~T)) << 32) | (unsigned long long)(base + found);
        last = found;
        __syncthreads();
    }

    if (tid < 64) g_cand[(b * NCHUNK + c) * KKP + tid] = cand[tid];
}

__global__ void __launch_bounds__(512) topk_stage2() {
    const int b = blockIdx.x;
    const int tid = threadIdx.x;
    __shared__ unsigned long long s[512];
    s[tid] = g_cand[b * 512 + tid];
    __syncthreads();

    for (int ksz = 2; ksz <= 512; ksz <<= 1) {
        for (int j = ksz >> 1; j > 0; j >>= 1) {
            int ixj = tid ^ j;
            if (ixj > tid) {
                bool up = ((tid & ksz) == 0);
                unsigned long long a = s[tid], c = s[ixj];
                if ((a > c) == up) { s[tid] = c; s[ixj] = a; }
            }
            __syncthreads();
        }
    }
    if (tid < KKP) g_kp[b * KKP + tid] = (int)(s[tid] & 0xFFFFFFFFULL);
}

// ==================== 3. patch extraction + conv3x3 + relu -> bf16 hi/lo ====================
__global__ void __launch_bounds__(256) patch_conv_kernel(const float* __restrict__ x,
                                                         const float* __restrict__ conv_w,
                                                         const float* __restrict__ conv_b) {
    __shared__ float sp[3][16][16];
    __shared__ float sw[8 * 27];
    __shared__ float sb[8];

    const int p  = blockIdx.x;
    const int b  = p >> 6;
    const int kk = p & 63;
    const int tid = threadIdx.x;

    if (tid < 216) sw[tid] = conv_w[tid];
    else if (tid < 224) sb[tid - 216] = conv_b[tid - 216];

    const int idx = g_kp[b * KKP + kk];
    const float rowf = (float)(idx / W_IMG);
    const float colf = (float)(idx % W_IMG);
    float cy = fminf(fmaxf((rowf / 224.0f - 0.5f) * 2.0f, -1.0f), 1.0f);
    float cx = fminf(fmaxf((colf / 224.0f - 0.5f) * 2.0f, -1.0f), 1.0f);
    float y01 = (cy + 1.0f) * 0.5f;
    float x01 = (cx + 1.0f) * 0.5f;

    const float rf = 16.0f / 224.0f;
    const float step = (2.0f * rf) / 15.0f;

    for (int s = tid; s < 768; s += 256) {
        int c = s >> 8;
        int pos = s & 255;
        int i = pos >> 4, j = pos & 15;
        float pgj = (j == 15) ? rf : (-rf + (float)j * step);
        float pgi = (i == 15) ? rf : (-rf + (float)i * step);
        // faithful to reference's swapped broadcast: grid_x uses row(y01), grid_y uses col(x01)
        float gxn = (pgj + y01) * 2.0f - 1.0f;
        float gyn = (pgi + x01) * 2.0f - 1.0f;
        float gx = (gxn + 1.0f) * 0.5f * 223.0f;
        float gy = (gyn + 1.0f) * 0.5f * 223.0f;

        float x0f = floorf(gx), y0f = floorf(gy);
        float wx1 = gx - x0f, wx0 = 1.0f - wx1;
        float wy1 = gy - y0f, wy0 = 1.0f - wy1;
        int x0 = (int)x0f, y0 = (int)y0f;

        // all taps provably in-bounds (keypoints masked to [16,208)^2, window < +-17px)
        const float* row0 = x + ((size_t)b * 3 + c) * NPIX + y0 * W_IMG + x0;
        const float* row1 = row0 + W_IMG;
        float v00 = __ldg(row0), v01 = __ldg(row0 + 1);
        float v10 = __ldg(row1), v11 = __ldg(row1 + 1);
        sp[c][i][j] = v00 * (wx0 * wy0) + v01 * (wx1 * wy0)
                    + v10 * (wx0 * wy1) + v11 * (wx1 * wy1);
    }
    __syncthreads();

    const int i = tid >> 4, j = tid & 15;
    float nb[3][3][3];
#pragma unroll
    for (int ci = 0; ci < 3; ci++)
#pragma unroll
        for (int u = 0; u < 3; u++)
#pragma unroll
            for (int v = 0; v < 3; v++) {
                int iy = i + u - 1, ix = j + v - 1;
                nb[ci][u][v] = (iy >= 0 && iy < 16 && ix >= 0 && ix < 16) ? sp[ci][iy][ix] : 0.0f;
            }

#pragma unroll
    for (int co = 0; co < 8; co++) {
        float acc = sb[co];
#pragma unroll
        for (int ci = 0; ci < 3; ci++)
#pragma unroll
            for (int u = 0; u < 3; u++)
#pragma unroll
                for (int v = 0; v < 3; v++)
                    acc += nb[ci][u][v] * sw[co * 27 + ci * 9 + u * 3 + v];
        float r = fmaxf(acc, 0.0f);
        __nv_bfloat16 h = __float2bfloat16(r);
        size_t o = (size_t)p * FEAT + co * 256 + tid;
        g_H1h[o] = h;
        g_H1l[o] = __float2bfloat16(r - __bfloat162float(h));
    }
}

// ==================== 4. fc1 via wmma bf16 hi/lo (exact compensation) ====================
// block = 8 warps covering 64m x 64n; grid (NPATCH/64, FC1_SPLIT); K-slice 512/block.
__global__ void __launch_bounds__(256) fc1_wmma() {
    const int w  = threadIdx.x >> 5;
    const int wm = w & 3;            // m16 tile within 64
    const int wn = w >> 2;           // n32 half
    const int m0 = blockIdx.x * 64 + wm * 16;
    const int n0 = wn * 32;
    const int k0 = blockIdx.y * (FEAT / FC1_SPLIT);

    wmma::fragment<wmma::accumulator, 16, 16, 16, float> acc0, acc1;
    wmma::fill_fragment(acc0, 0.0f);
    wmma::fill_fragment(acc1, 0.0f);

    for (int k = k0; k < k0 + FEAT / FC1_SPLIT; k += 16) {
        wmma::fragment<wmma::matrix_a, 16, 16, 16, __nv_bfloat16, wmma::row_major> ah, al;
        wmma::fragment<wmma::matrix_b, 16, 16, 16, __nv_bfloat16, wmma::col_major> bh0, bl0, bh1, bl1;
        wmma::load_matrix_sync(ah, g_H1h + (size_t)m0 * FEAT + k, FEAT);
        wmma::load_matrix_sync(al, g_H1l + (size_t)m0 * FEAT + k, FEAT);
        // W is [n][k] row-major == [k][n] col-major with ld=FEAT
        wmma::load_matrix_sync(bh0, g_Wh + (size_t)n0 * FEAT + k, FEAT);
        wmma::load_matrix_sync(bl0, g_Wl + (size_t)n0 * FEAT + k, FEAT);
        wmma::load_matrix_sync(bh1, g_Wh + (size_t)(n0 + 16) * FEAT + k, FEAT);
        wmma::load_matrix_sync(bl1, g_Wl + (size_t)(n0 + 16) * FEAT + k, FEAT);
        wmma::mma_sync(acc0, ah, bh0, acc0);
        wmma::mma_sync(acc0, ah, bl0, acc0);
        wmma::mma_sync(acc0, al, bh0, acc0);
        wmma::mma_sync(acc0, al, bl0, acc0);
        wmma::mma_sync(acc1, ah, bh1, acc1);
        wmma::mma_sync(acc1, ah, bl1, acc1);
        wmma::mma_sync(acc1, al, bh1, acc1);
        wmma::mma_sync(acc1, al, bl1, acc1);
    }

    float* Cp = g_Cpart + (size_t)blockIdx.y * (NPATCH * FC1OUT)
              + (size_t)m0 * FC1OUT + n0;
    wmma::store_matrix_sync(Cp, acc0, FC1OUT, wmma::mem_row_major);
    wmma::store_matrix_sync(Cp + 16, acc1, FC1OUT, wmma::mem_row_major);
}

// sum partials + bias + relu, write TRANSPOSED activations g_H2T[kappa][b]
__global__ void __launch_bounds__(256) fc1_finish(const float* __restrict__ fc1_b) {
    int idx = blockIdx.x * 256 + threadIdx.x;   // < 131072
    int o = idx & 63;
    float v = fc1_b[o];
#pragma unroll
    for (int s = 0; s < FC1_SPLIT; s++)
        v += g_Cpart[(size_t)s * (NPATCH * FC1OUT) + idx];
    int p = idx >> 6;
    int b = p >> 6;
    int kappa = (p & 63) * 64 + o;
    g_H2T[kappa * BATCH + b] = fmaxf(v, 0.0f);
}

// ==================== 5. fc2 GEMM (round-14 proven) ====================
__global__ void __launch_bounds__(256) fc2_kernel(const float* __restrict__ w2) {
    __shared__ float sH[64][32];
    __shared__ float sW[64][68];

    const int n0 = blockIdx.x * 64;
    const int kb = blockIdx.y * (FC2IN / FC2_SPLIT);
    const int t = threadIdx.x;
    const int tb4 = (t & 7) * 4;
    const int tn  = (t >> 3) * 2;

    float acc[4][2];
#pragma unroll
    for (int bi = 0; bi < 4; bi++) { acc[bi][0] = 0.f; acc[bi][1] = 0.f; }

    for (int kc = 0; kc < FC2IN / FC2_SPLIT; kc += 64) {
#pragma unroll
        for (int r = 0; r < 2; r++) {
            int q = t + r * 256;
            int k = q >> 3, b4 = (q & 7) * 4;
            *(float4*)&sH[k][b4] = *(const float4*)&g_H2T[(size_t)(kb + kc + k) * BATCH + b4];
        }
#pragma unroll
        for (int r = 0; r < 4; r++) {
            int q = t + r * 256;
            int n = q >> 4, k4 = (q & 15) * 4;
            int gn = n0 + n;
            float4 v = (gn < NCLASS) ? *(const float4*)&w2[(size_t)gn * FC2IN + kb + kc + k4]
                                     : make_float4(0.f, 0.f, 0.f, 0.f);
            *(float4*)&sW[n][k4] = v;
        }
        __syncthreads();
#pragma unroll
        for (int k4 = 0; k4 < 64; k4 += 4) {
            float4 w0 = *(const float4*)&sW[tn][k4];
            float4 w1 = *(const float4*)&sW[tn + 1][k4];
            float4 h0 = *(const float4*)&sH[k4 + 0][tb4];
            float4 h1 = *(const float4*)&sH[k4 + 1][tb4];
            float4 h2 = *(const float4*)&sH[k4 + 2][tb4];
            float4 h3 = *(const float4*)&sH[k4 + 3][tb4];
            acc[0][0] = fmaf(h0.x, w0.x, acc[0][0]); acc[0][1] = fmaf(h0.x, w1.x, acc[0][1]);
            acc[1][0] = fmaf(h0.y, w0.x, acc[1][0]); acc[1][1] = fmaf(h0.y, w1.x, acc[1][1]);
            acc[2][0] = fmaf(h0.z, w0.x, acc[2][0]); acc[2][1] = fmaf(h0.z, w1.x, acc[2][1]);
            acc[3][0] = fmaf(h0.w, w0.x, acc[3][0]); acc[3][1] = fmaf(h0.w, w1.x, acc[3][1]);
            acc[0][0] = fmaf(h1.x, w0.y, acc[0][0]); acc[0][1] = fmaf(h1.x, w1.y, acc[0][1]);
            acc[1][0] = fmaf(h1.y, w0.y, acc[1][0]); acc[1][1] = fmaf(h1.y, w1.y, acc[1][1]);
            acc[2][0] = fmaf(h1.z, w0.y, acc[2][0]); acc[2][1] = fmaf(h1.z, w1.y, acc[2][1]);
            acc[3][0] = fmaf(h1.w, w0.y, acc[3][0]); acc[3][1] = fmaf(h1.w, w1.y, acc[3][1]);
            acc[0][0] = fmaf(h2.x, w0.z, acc[0][0]); acc[0][1] = fmaf(h2.x, w1.z, acc[0][1]);
            acc[1][0] = fmaf(h2.y, w0.z, acc[1][0]); acc[1][1] = fmaf(h2.y, w1.z, acc[1][1]);
            acc[2][0] = fmaf(h2.z, w0.z, acc[2][0]); acc[2][1] = fmaf(h2.z, w1.z, acc[2][1]);
            acc[3][0] = fmaf(h2.w, w0.z, acc[3][0]); acc[3][1] = fmaf(h2.w, w1.z, acc[3][1]);
            acc[0][0] = fmaf(h3.x, w0.w, acc[0][0]); acc[0][1] = fmaf(h3.x, w1.w, acc[0][1]);
            acc[1][0] = fmaf(h3.y, w0.w, acc[1][0]); acc[1][1] = fmaf(h3.y, w1.w, acc[1][1]);
            acc[2][0] = fmaf(h3.z, w0.w, acc[2][0]); acc[2][1] = fmaf(h3.z, w1.w, acc[2][1]);
            acc[3][0] = fmaf(h3.w, w0.w, acc[3][0]); acc[3][1] = fmaf(h3.w, w1.w, acc[3][1]);
        }
        __syncthreads();
    }

    float* Fp = g_F2p + (size_t)blockIdx.y * (BATCH * NCLASS);
#pragma unroll
    for (int bi = 0; bi < 4; bi++)
#pragma unroll
        for (int ni = 0; ni < 2; ni++) {
            int n = n0 + tn + ni;
            if (n < NCLASS) Fp[(tb4 + bi) * NCLASS + n] = acc[bi][ni];
        }
}

__global__ void __launch_bounds__(256) fc2_finish(const float* __restrict__ b2,
                                                  float* __restrict__ out) {
    int idx = blockIdx.x * 256 + threadIdx.x;
    if (idx >= BATCH * NCLASS) return;
    int n = idx % NCLASS;
    float v = b2[n];
#pragma unroll
    for (int s = 0; s < FC2_SPLIT; s++)
        v += g_F2p[(size_t)s * (BATCH * NCLASS) + idx];
    out[idx] = v;
}

// ==================== launch ====================
extern "C" void kernel_launch(void* const* d_in, const int* in_sizes, int n_in,
                              void* d_out, int out_size) {
    const float* x      = (const float*)d_in[0];
    const float* conv_w = (const float*)d_in[1];
    const float* conv_b = (const float*)d_in[2];
    const float* fc1_w  = (const float*)d_in[3];
    const float* fc1_b  = (const float*)d_in[4];
    const float* fc2_w  = (const float*)d_in[5];
    const float* fc2_b  = (const float*)d_in[6];
    float* out = (float*)d_out;

    cudaFuncSetAttribute(topk_stage1, cudaFuncAttributeMaxDynamicSharedMemorySize,
                         SM_TOPK_TOTAL);

    prep_w<<<FC1OUT * FEAT / 256, 256>>>(fc1_w);
    topk_stage1<<<dim3(NCHUNK, BATCH), 512, SM_TOPK_TOTAL>>>(x);
    topk_stage2<<<BATCH, 512>>>();
    patch_conv_kernel<<<NPATCH, 256>>>(x, conv_w, conv_b);
    fc1_wmma<<<dim3(NPATCH / 64, FC1_SPLIT), 256>>>();
    fc1_finish<<<512, 256>>>(fc1_b);
    fc2_kernel<<<dim3((NCLASS + 63) / 64, FC2_SPLIT), 256>>>(fc2_w);
    fc2_finish<<<(BATCH * NCLASS + 255) / 256, 256>>>(fc2_b, out);
}

// round 17
// speedup vs baseline: 1.2030x; 1.2030x over previous
#include <cuda_runtime.h>
#include <cuda_bf16.h>
#include <mma.h>
#include <cstdint>

using namespace nvcuda;

#define H_IMG 224
#define W_IMG 224
#define NPIX (H_IMG * W_IMG)          // 50176
#define BATCH 32
#define KKP 64
#define PATCH 16
#define NCLASS 1000
#define NPATCH (BATCH * KKP)          // 2048
#define FEAT 2048                      // 8*16*16
#define FC1OUT 64
#define FC2IN (KKP * FC1OUT)          // 4096
#define NCHUNK 8
#define CHUNKROWS 28
#define CHUNK (NPIX / NCHUNK)         // 6272
#define FC1_SPLIT 8
#define FC2_SPLIT 16

// dynamic smem layout for fused harris+topk
#define SM_KEYS 0
#define SM_GRAY 25088
#define SM_DXS  (SM_GRAY + 32 * 228 * 4)
#define SM_DYS  (SM_DXS + 30 * 198 * 4)
#define SM_TOPK_TOTAL (SM_DYS + 30 * 198 * 4)  // 101792

// -------------------- device scratch --------------------
__device__ unsigned long long g_cand[BATCH * NCHUNK * KKP];
__device__ int   g_kp[BATCH * KKP];
__device__ __nv_bfloat16 g_H1h[NPATCH * FEAT];
__device__ __nv_bfloat16 g_H1l[NPATCH * FEAT];
__device__ __nv_bfloat16 g_Wh[FC1OUT * FEAT];
__device__ __nv_bfloat16 g_Wl[FC1OUT * FEAT];
__device__ float g_Cpart[FC1_SPLIT * NPATCH * FC1OUT];
__device__ float g_H2T[FC2IN * BATCH];
__device__ float g_F2p[FC2_SPLIT * BATCH * NCLASS];

// ==================== 0. split fc1 weights to bf16 hi/lo ====================
__global__ void __launch_bounds__(256) prep_w(const float* __restrict__ w) {
    int i = blockIdx.x * 256 + threadIdx.x;   // < 131072
    float v = w[i];
    __nv_bfloat16 h = __float2bfloat16(v);
    g_Wh[i] = h;
    g_Wl[i] = __float2bfloat16(v - __bfloat162float(h));
}

// ==================== 1+2. fused Harris + exact per-chunk top-64 ====================
__device__ __forceinline__ unsigned int fkey(float f) {
    unsigned int u = __float_as_uint(f);
    return (u & 0x80000000u) ? ~u : (u | 0x80000000u);
}
__device__ __forceinline__ void hist_add(unsigned int* hist, int bin) {
    unsigned int act = __activemask();
    unsigned int same = __match_any_sync(act, bin);
    int leader = __ffs(same) - 1;
    if ((int)(threadIdx.x & 31) == leader)
        atomicAdd(&hist[bin], (unsigned int)__popc(same));
}

__global__ void __launch_bounds__(512) topk_stage1(const float* __restrict__ x) {
    extern __shared__ char smraw[];
    unsigned int* keys = (unsigned int*)(smraw + SM_KEYS);
    float* gray = (float*)(smraw + SM_GRAY);
    float* dxs  = (float*)(smraw + SM_DXS);
    float* dys  = (float*)(smraw + SM_DYS);

    __shared__ unsigned int hist[256];
    __shared__ unsigned int suf[256];
    __shared__ unsigned int sh_prefix;
    __shared__ int sh_kneed;
    __shared__ unsigned long long cand[64];
    __shared__ int sh_cnt;
    __shared__ int sh_min;

    const int c = blockIdx.x;
    const int b = blockIdx.y;
    const int tid = threadIdx.x;
    const int r0 = c * CHUNKROWS;
    const int base = r0 * W_IMG;
    const float* xb = x + (size_t)b * 3 * NPIX;

    if (tid < 256) hist[tid] = 0u;

    for (int i = tid; i < 32 * W_IMG; i += 512) {
        int gr = i / W_IMG, col = i - (i / W_IMG) * W_IMG;
        int row = r0 - 2 + gr;
        float v = 0.0f;
        if (row >= 0 && row < H_IMG) {
            int off = row * W_IMG + col;
            v = (xb[off] + xb[NPIX + off] + xb[2 * NPIX + off]) / 3.0f;
        }
        gray[gr * 228 + col] = v;
    }
    __syncthreads();

    const int outMin = max(r0, PATCH);
    const int outMax = min(r0 + CHUNKROWS - 1, H_IMG - PATCH - 1);
    const int dRow0 = outMin - 1;
    const int nDRows = outMax + 1 - dRow0 + 1;

    for (int i = tid; i < nDRows * 194; i += 512) {
        int dr = i / 194, dc = i - dr * 194;
        int Y = dRow0 + dr;
        int X = 15 + dc;
        int g0 = (Y - 1 - (r0 - 2)) * 228 + X;
        float gm1l = gray[g0 - 1],        gm1c = gray[g0],        gm1r = gray[g0 + 1];
        float g0l  = gray[g0 + 228 - 1],                          g0r  = gray[g0 + 228 + 1];
        float gp1l = gray[g0 + 456 - 1],  gp1c = gray[g0 + 456],  gp1r = gray[g0 + 456 + 1];
        float lft = gm1l + g0l + gp1l;
        float rgt = gm1r + g0r + gp1r;
        float top = gm1l + gm1c + gm1r;
        float bot = gp1l + gp1c + gp1r;
        dxs[dr * 198 + dc] = rgt - lft;
        dys[dr * 198 + dc] = bot - top;
    }
    __syncthreads();

    const float GW[3][3] = {{0.0625f, 0.125f, 0.0625f},
                            {0.125f,  0.25f,  0.125f},
                            {0.0625f, 0.125f, 0.0625f}};
    for (int i = tid; i < CHUNK; i += 512) {
        int lr = i / W_IMG;
        int col = i - lr * W_IMG;
        int row = r0 + lr;
        unsigned int key = 0x80000000u;
        if (row >= PATCH && row < H_IMG - PATCH && col >= PATCH && col < W_IMG - PATCH) {
            float sxx = 0.f, syy = 0.f, sxy = 0.f;
            int dbase = (row - 1 - dRow0) * 198 + (col - 1 - 15);
#pragma unroll
            for (int u = 0; u < 3; u++)
#pragma unroll
                for (int v = 0; v < 3; v++) {
                    float w = GW[u][v];
                    float a = dxs[dbase + u * 198 + v];
                    float d = dys[dbase + u * 198 + v];
                    sxx += w * (a * a);
                    syy += w * (d * d);
                    sxy += w * (a * d);
                }
            float tr = sxx + syy;
            float R = sxx * syy - sxy * sxy - 0.04f * tr * tr;
            key = fkey(R);
        }
        keys[i] = key;
        hist_add(hist, key >> 24);
    }
    __syncthreads();

    unsigned int prefix = 0;
    int kneed = KKP;
    for (int level = 0; level < 4; level++) {
        int shift = 24 - 8 * level;
        if (level > 0) {
            if (tid < 256) hist[tid] = 0u;
            __syncthreads();
            for (int i = tid; i < CHUNK; i += 512) {
                unsigned int u = keys[i];
                if ((u >> (shift + 8)) == (prefix >> (shift + 8)))
                    hist_add(hist, (u >> shift) & 0xFFu);
            }
            __syncthreads();
        }
        if (tid < 256) suf[tid] = hist[tid];
        __syncthreads();
#pragma unroll
        for (int off = 1; off < 256; off <<= 1) {
            unsigned int add = 0;
            if (tid < 256 && tid + off < 256) add = suf[tid + off];
            __syncthreads();
            if (tid < 256) suf[tid] += add;
            __syncthreads();
        }
        if (tid < 256) {
            unsigned int ge = suf[tid];
            unsigned int gt = (tid == 255) ? 0u : suf[tid + 1];
            if (ge >= (unsigned int)kneed && gt < (unsigned int)kneed) {
                sh_kneed = kneed - (int)gt;
                sh_prefix = prefix | ((unsigned int)tid << shift);
            }
        }
        __syncthreads();
        prefix = sh_prefix;
        kneed = sh_kneed;
        __syncthreads();
    }

    const unsigned int T = prefix;
    const int cGT = KKP - kneed;

    if (tid == 0) sh_cnt = 0;
    __syncthreads();
    for (int i = tid; i < CHUNK; i += 512) {
        unsigned int u = keys[i];
        if (u > T) {
            int pos = atomicAdd(&sh_cnt, 1);
            cand[pos] = (((unsigned long long)(~u)) << 32) | (unsigned long long)(base + i);
        }
    }
    __syncthreads();

    int last = -1;
    for (int t = 0; t < kneed; t++) {
        if (tid == 0) sh_min = CHUNK;
        __syncthreads();
        for (int i = tid; i < CHUNK; i += 512)
            if (i > last && keys[i] == T) atomicMin(&sh_min, i);
        __syncthreads();
        int found = sh_min;
        if (tid == 0)
            cand[cGT + t] = (((unsigned long long)(~T)) << 32) | (unsigned long long)(base + found);
        last = found;
        __syncthreads();
    }

    if (tid < 64) g_cand[(b * NCHUNK + c) * KKP + tid] = cand[tid];
}

__global__ void __launch_bounds__(512) topk_stage2() {
    const int b = blockIdx.x;
    const int tid = threadIdx.x;
    __shared__ unsigned long long s[512];
    s[tid] = g_cand[b * 512 + tid];
    __syncthreads();

    for (int ksz = 2; ksz <= 512; ksz <<= 1) {
        for (int j = ksz >> 1; j > 0; j >>= 1) {
            int ixj = tid ^ j;
            if (ixj > tid) {
                bool up = ((tid & ksz) == 0);
                unsigned long long a = s[tid], c = s[ixj];
                if ((a > c) == up) { s[tid] = c; s[ixj] = a; }
            }
            __syncthreads();
        }
    }
    if (tid < KKP) g_kp[b * KKP + tid] = (int)(s[tid] & 0xFFFFFFFFULL);
}

// ==================== 3. patch extraction + conv3x3 + relu -> bf16 hi/lo ====================
__global__ void __launch_bounds__(256) patch_conv_kernel(const float* __restrict__ x,
                                                         const float* __restrict__ conv_w,
                                                         const float* __restrict__ conv_b) {
    __shared__ float sp[3][16][16];
    __shared__ float sw[8 * 27];
    __shared__ float sb[8];

    const int p  = blockIdx.x;
    const int b  = p >> 6;
    const int kk = p & 63;
    const int tid = threadIdx.x;

    if (tid < 216) sw[tid] = conv_w[tid];
    else if (tid < 224) sb[tid - 216] = conv_b[tid - 216];

    const int idx = g_kp[b * KKP + kk];
    const float rowf = (float)(idx / W_IMG);
    const float colf = (float)(idx % W_IMG);
    float cy = fminf(fmaxf((rowf / 224.0f - 0.5f) * 2.0f, -1.0f), 1.0f);
    float cx = fminf(fmaxf((colf / 224.0f - 0.5f) * 2.0f, -1.0f), 1.0f);
    float y01 = (cy + 1.0f) * 0.5f;
    float x01 = (cx + 1.0f) * 0.5f;

    const float rf = 16.0f / 224.0f;
    const float step = (2.0f * rf) / 15.0f;

    for (int s = tid; s < 768; s += 256) {
        int c = s >> 8;
        int pos = s & 255;
        int i = pos >> 4, j = pos & 15;
        float pgj = (j == 15) ? rf : (-rf + (float)j * step);
        float pgi = (i == 15) ? rf : (-rf + (float)i * step);
        // faithful to reference's swapped broadcast: grid_x uses row(y01), grid_y uses col(x01)
        float gxn = (pgj + y01) * 2.0f - 1.0f;
        float gyn = (pgi + x01) * 2.0f - 1.0f;
        float gx = (gxn + 1.0f) * 0.5f * 223.0f;
        float gy = (gyn + 1.0f) * 0.5f * 223.0f;

        float x0f = floorf(gx), y0f = floorf(gy);
        float wx1 = gx - x0f, wx0 = 1.0f - wx1;
        float wy1 = gy - y0f, wy0 = 1.0f - wy1;
        int x0 = (int)x0f, y0 = (int)y0f;

        // all taps provably in-bounds (keypoints masked to [16,208)^2, window < +-17px)
        const float* row0 = x + ((size_t)b * 3 + c) * NPIX + y0 * W_IMG + x0;
        const float* row1 = row0 + W_IMG;
        float v00 = __ldg(row0), v01 = __ldg(row0 + 1);
        float v10 = __ldg(row1), v11 = __ldg(row1 + 1);
        sp[c][i][j] = v00 * (wx0 * wy0) + v01 * (wx1 * wy0)
                    + v10 * (wx0 * wy1) + v11 * (wx1 * wy1);
    }
    __syncthreads();

    const int i = tid >> 4, j = tid & 15;
    float nb[3][3][3];
#pragma unroll
    for (int ci = 0; ci < 3; ci++)
#pragma unroll
        for (int u = 0; u < 3; u++)
#pragma unroll
            for (int v = 0; v < 3; v++) {
                int iy = i + u - 1, ix = j + v - 1;
                nb[ci][u][v] = (iy >= 0 && iy < 16 && ix >= 0 && ix < 16) ? sp[ci][iy][ix] : 0.0f;
            }

#pragma unroll
    for (int co = 0; co < 8; co++) {
        float acc = sb[co];
#pragma unroll
        for (int ci = 0; ci < 3; ci++)
#pragma unroll
            for (int u = 0; u < 3; u++)
#pragma unroll
                for (int v = 0; v < 3; v++)
                    acc += nb[ci][u][v] * sw[co * 27 + ci * 9 + u * 3 + v];
        float r = fmaxf(acc, 0.0f);
        __nv_bfloat16 h = __float2bfloat16(r);
        size_t o = (size_t)p * FEAT + co * 256 + tid;
        g_H1h[o] = h;
        g_H1l[o] = __float2bfloat16(r - __bfloat162float(h));
    }
}

// ==================== 4. fc1 via wmma bf16 hi/lo, SMEM-staged tiles ====================
// block: 8 warps, tile M=128 x N=64, K-chunks of 32; grid (16, FC1_SPLIT).
__global__ void __launch_bounds__(256) fc1_wmma() {
    __shared__ __nv_bfloat16 sAh[128][40];
    __shared__ __nv_bfloat16 sAl[128][40];
    __shared__ __nv_bfloat16 sBh[64][40];
    __shared__ __nv_bfloat16 sBl[64][40];

    const int tid = threadIdx.x;
    const int w = tid >> 5;                 // warp 0..7 -> m16 row
    const int m0 = blockIdx.x * 128;
    const int k0 = blockIdx.y * (FEAT / FC1_SPLIT);   // 256-wide slice

    wmma::fragment<wmma::accumulator, 16, 16, 16, float> acc[4];
#pragma unroll
    for (int nt = 0; nt < 4; nt++) wmma::fill_fragment(acc[nt], 0.0f);

    for (int kc = 0; kc < FEAT / FC1_SPLIT; kc += 32) {
        const int kb = k0 + kc;
        // fill A: 128 rows x 32 bf16 (uint4 = 8 bf16; 4 segs/row)
#pragma unroll
        for (int r = 0; r < 2; r++) {
            int idx = tid + r * 256;
            int m = idx >> 2, seg = idx & 3;
            *(uint4*)&sAh[m][seg * 8] = *(const uint4*)(g_H1h + (size_t)(m0 + m) * FEAT + kb + seg * 8);
            *(uint4*)&sAl[m][seg * 8] = *(const uint4*)(g_H1l + (size_t)(m0 + m) * FEAT + kb + seg * 8);
        }
        // fill B: 64 rows x 32 bf16
        {
            int m = tid >> 2, seg = tid & 3;
            if (m < 64) {
                *(uint4*)&sBh[m][seg * 8] = *(const uint4*)(g_Wh + (size_t)m * FEAT + kb + seg * 8);
                *(uint4*)&sBl[m][seg * 8] = *(const uint4*)(g_Wl + (size_t)m * FEAT + kb + seg * 8);
            }
        }
        __syncthreads();

#pragma unroll
        for (int ks = 0; ks < 2; ks++) {
            wmma::fragment<wmma::matrix_a, 16, 16, 16, __nv_bfloat16, wmma::row_major> ah, al;
            wmma::load_matrix_sync(ah, &sAh[w * 16][ks * 16], 40);
            wmma::load_matrix_sync(al, &sAl[w * 16][ks * 16], 40);
#pragma unroll
            for (int nt = 0; nt < 4; nt++) {
                wmma::fragment<wmma::matrix_b, 16, 16, 16, __nv_bfloat16, wmma::col_major> bh, bl;
                wmma::load_matrix_sync(bh, &sBh[nt * 16][ks * 16], 40);
                wmma::load_matrix_sync(bl, &sBl[nt * 16][ks * 16], 40);
                wmma::mma_sync(acc[nt], ah, bh, acc[nt]);
                wmma::mma_sync(acc[nt], ah, bl, acc[nt]);
                wmma::mma_sync(acc[nt], al, bh, acc[nt]);
                wmma::mma_sync(acc[nt], al, bl, acc[nt]);
            }
        }
        __syncthreads();
    }

    float* Cp = g_Cpart + (size_t)blockIdx.y * (NPATCH * FC1OUT)
              + (size_t)(m0 + w * 16) * FC1OUT;
#pragma unroll
    for (int nt = 0; nt < 4; nt++)
        wmma::store_matrix_sync(Cp + nt * 16, acc[nt], FC1OUT, wmma::mem_row_major);
}

// sum partials + bias + relu, write TRANSPOSED activations g_H2T[kappa][b]
__global__ void __launch_bounds__(256) fc1_finish(const float* __restrict__ fc1_b) {
    int idx = blockIdx.x * 256 + threadIdx.x;   // < 131072
    int o = idx & 63;
    float v = fc1_b[o];
#pragma unroll
    for (int s = 0; s < FC1_SPLIT; s++)
        v += g_Cpart[(size_t)s * (NPATCH * FC1OUT) + idx];
    int p = idx >> 6;
    int b = p >> 6;
    int kappa = (p & 63) * 64 + o;
    g_H2T[kappa * BATCH + b] = fmaxf(v, 0.0f);
}

// ==================== 5. fc2 GEMM (round-14 proven) ====================
__global__ void __launch_bounds__(256) fc2_kernel(const float* __restrict__ w2) {
    __shared__ float sH[64][32];
    __shared__ float sW[64][68];

    const int n0 = blockIdx.x * 64;
    const int kb = blockIdx.y * (FC2IN / FC2_SPLIT);
    const int t = threadIdx.x;
    const int tb4 = (t & 7) * 4;
    const int tn  = (t >> 3) * 2;

    float acc[4][2];
#pragma unroll
    for (int bi = 0; bi < 4; bi++) { acc[bi][0] = 0.f; acc[bi][1] = 0.f; }

    for (int kc = 0; kc < FC2IN / FC2_SPLIT; kc += 64) {
#pragma unroll
        for (int r = 0; r < 2; r++) {
            int q = t + r * 256;
            int k = q >> 3, b4 = (q & 7) * 4;
            *(float4*)&sH[k][b4] = *(const float4*)&g_H2T[(size_t)(kb + kc + k) * BATCH + b4];
        }
#pragma unroll
        for (int r = 0; r < 4; r++) {
            int q = t + r * 256;
            int n = q >> 4, k4 = (q & 15) * 4;
            int gn = n0 + n;
            float4 v = (gn < NCLASS) ? *(const float4*)&w2[(size_t)gn * FC2IN + kb + kc + k4]
                                     : make_float4(0.f, 0.f, 0.f, 0.f);
            *(float4*)&sW[n][k4] = v;
        }
        __syncthreads();
#pragma unroll
        for (int k4 = 0; k4 < 64; k4 += 4) {
            float4 w0 = *(const float4*)&sW[tn][k4];
            float4 w1 = *(const float4*)&sW[tn + 1][k4];
            float4 h0 = *(const float4*)&sH[k4 + 0][tb4];
            float4 h1 = *(const float4*)&sH[k4 + 1][tb4];
            float4 h2 = *(const float4*)&sH[k4 + 2][tb4];
            float4 h3 = *(const float4*)&sH[k4 + 3][tb4];
            acc[0][0] = fmaf(h0.x, w0.x, acc[0][0]); acc[0][1] = fmaf(h0.x, w1.x, acc[0][1]);
            acc[1][0] = fmaf(h0.y, w0.x, acc[1][0]); acc[1][1] = fmaf(h0.y, w1.x, acc[1][1]);
            acc[2][0] = fmaf(h0.z, w0.x, acc[2][0]); acc[2][1] = fmaf(h0.z, w1.x, acc[2][1]);
            acc[3][0] = fmaf(h0.w, w0.x, acc[3][0]); acc[3][1] = fmaf(h0.w, w1.x, acc[3][1]);
            acc[0][0] = fmaf(h1.x, w0.y, acc[0][0]); acc[0][1] = fmaf(h1.x, w1.y, acc[0][1]);
            acc[1][0] = fmaf(h1.y, w0.y, acc[1][0]); acc[1][1] = fmaf(h1.y, w1.y, acc[1][1]);
            acc[2][0] = fmaf(h1.z, w0.y, acc[2][0]); acc[2][1] = fmaf(h1.z, w1.y, acc[2][1]);
            acc[3][0] = fmaf(h1.w, w0.y, acc[3][0]); acc[3][1] = fmaf(h1.w, w1.y, acc[3][1]);
            acc[0][0] = fmaf(h2.x, w0.z, acc[0][0]); acc[0][1] = fmaf(h2.x, w1.z, acc[0][1]);
            acc[1][0] = fmaf(h2.y, w0.z, acc[1][0]); acc[1][1] = fmaf(h2.y, w1.z, acc[1][1]);
            acc[2][0] = fmaf(h2.z, w0.z, acc[2][0]); acc[2][1] = fmaf(h2.z, w1.z, acc[2][1]);
            acc[3][0] = fmaf(h2.w, w0.z, acc[3][0]); acc[3][1] = fmaf(h2.w, w1.z, acc[3][1]);
            acc[0][0] = fmaf(h3.x, w0.w, acc[0][0]); acc[0][1] = fmaf(h3.x, w1.w, acc[0][1]);
            acc[1][0] = fmaf(h3.y, w0.w, acc[1][0]); acc[1][1] = fmaf(h3.y, w1.w, acc[1][1]);
            acc[2][0] = fmaf(h3.z, w0.w, acc[2][0]); acc[2][1] = fmaf(h3.z, w1.w, acc[2][1]);
            acc[3][0] = fmaf(h3.w, w0.w, acc[3][0]); acc[3][1] = fmaf(h3.w, w1.w, acc[3][1]);
        }
        __syncthreads();
    }

    float* Fp = g_F2p + (size_t)blockIdx.y * (BATCH * NCLASS);
#pragma unroll
    for (int bi = 0; bi < 4; bi++)
#pragma unroll
        for (int ni = 0; ni < 2; ni++) {
            int n = n0 + tn + ni;
            if (n < NCLASS) Fp[(tb4 + bi) * NCLASS + n] = acc[bi][ni];
        }
}

__global__ void __launch_bounds__(256) fc2_finish(const float* __restrict__ b2,
                                                  float* __restrict__ out) {
    int idx = blockIdx.x * 256 + threadIdx.x;
    if (idx >= BATCH * NCLASS) return;
    int n = idx % NCLASS;
    float v = b2[n];
#pragma unroll
    for (int s = 0; s < FC2_SPLIT; s++)
        v += g_F2p[(size_t)s * (BATCH * NCLASS) + idx];
    out[idx] = v;
}

// ==================== launch ====================
extern "C" void kernel_launch(void* const* d_in, const int* in_sizes, int n_in,
                              void* d_out, int out_size) {
    const float* x      = (const float*)d_in[0];
    const float* conv_w = (const float*)d_in[1];
    const float* conv_b = (const float*)d_in[2];
    const float* fc1_w  = (const float*)d_in[3];
    const float* fc1_b  = (const float*)d_in[4];
    const float* fc2_w  = (const float*)d_in[5];
    const float* fc2_b  = (const float*)d_in[6];
    float* out = (float*)d_out;

    cudaFuncSetAttribute(topk_stage1, cudaFuncAttributeMaxDynamicSharedMemorySize,
                         SM_TOPK_TOTAL);

    prep_w<<<FC1OUT * FEAT / 256, 256>>>(fc1_w);
    topk_stage1<<<dim3(NCHUNK, BATCH), 512, SM_TOPK_TOTAL>>>(x);
    topk_stage2<<<BATCH, 512>>>();
    patch_conv_kernel<<<NPATCH, 256>>>(x, conv_w, conv_b);
    fc1_wmma<<<dim3(NPATCH / 128, FC1_SPLIT), 256>>>();
    fc1_finish<<<512, 256>>>(fc1_b);
    fc2_kernel<<<dim3((NCLASS + 63) / 64, FC2_SPLIT), 256>>>(fc2_w);
    fc2_finish<<<(BATCH * NCLASS + 255) / 256, 256>>>(fc2_b, out);
}